// round 17
// baseline (speedup 1.0000x reference)
#include <cuda_runtime.h>
#include <cuda_bf16.h>
#include <stdint.h>

#define BB 4096
#define DD 1024
#define RR 256
#define NCTA 128
#define NTHR 512

#define K_W1 1.3512071919596578
#define K_W0 (-1.7024143839193153)
#define K_C1f ((float)(K_W1 * 0.5))
#define K_C2f ((float)((K_W0 + K_W1) * 0.5))
#define K_DT 0.01f

__device__ __align__(1024) unsigned char g_Ub[16 * 32768];   // U bf16: 16 k-chunks [256n x 64k] SW128
__device__ __align__(1024) unsigned char g_Wb[64 * 8192];    // W bf16: 16 n-chunks x 4 k-tiles [64n x 64k] SW128
__device__ __align__(1024) float g_vf[(size_t)BB * DD];      // v fp32 master

__device__ __forceinline__ uint32_t swz(uint32_t o) { return o ^ ((o >> 3) & 0x70); }
__device__ __forceinline__ uint32_t s2u(const void* p) {
    uint32_t a; asm("{ .reg .u64 t; cvta.to.shared.u64 t, %1; cvt.u32.u64 %0, t; }" : "=r"(a) : "l"(p)); return a;
}
__device__ __forceinline__ uint32_t bf2u(__nv_bfloat162 b) { return *reinterpret_cast<uint32_t*>(&b); }
__device__ __forceinline__ void mb_init(uint32_t a, uint32_t c) {
    asm volatile("mbarrier.init.shared.b64 [%0], %1;" :: "r"(a), "r"(c) : "memory");
}
__device__ __forceinline__ void mb_expect(uint32_t a, uint32_t b) {
    asm volatile("mbarrier.arrive.expect_tx.shared.b64 _, [%0], %1;" :: "r"(a), "r"(b) : "memory");
}
__device__ __forceinline__ void mb_wait(uint32_t a, uint32_t p) {
    asm volatile("{\n\t.reg .pred P;\n\tLW%=:\n\t"
        "mbarrier.try_wait.parity.acquire.cta.shared::cta.b64 P, [%0], %1, 0x989680;\n\t"
        "@P bra LD%=;\n\tbra LW%=;\n\tLD%=:\n\t}" :: "r"(a), "r"(p) : "memory");
}
__device__ __forceinline__ void bulkcp(uint32_t d, const void* s, uint32_t n, uint32_t mb) {
    asm volatile("cp.async.bulk.shared::cluster.global.mbarrier::complete_tx::bytes [%0], [%1], %2, [%3];"
                 :: "r"(d), "l"(s), "r"(n), "r"(mb) : "memory");
}
__device__ __forceinline__ void fence_async_sh() { asm volatile("fence.proxy.async.shared::cta;" ::: "memory"); }
__device__ __forceinline__ void nbar_sync(int id, int cnt) {
    asm volatile("bar.sync %0, %1;" :: "r"(id), "r"(cnt) : "memory");
}
__device__ __forceinline__ void nbar_arrive(int id, int cnt) {
    asm volatile("bar.arrive %0, %1;" :: "r"(id), "r"(cnt) : "memory");
}
__device__ __forceinline__ void ldsm4(uint32_t* r, uint32_t a) {
    asm volatile("ldmatrix.sync.aligned.m8n8.x4.shared.b16 {%0,%1,%2,%3}, [%4];"
                 : "=r"(r[0]), "=r"(r[1]), "=r"(r[2]), "=r"(r[3]) : "r"(a));
}
__device__ __forceinline__ void mma16816(float* c, const uint32_t* a, const uint32_t* b) {
    asm volatile("mma.sync.aligned.m16n8k16.row.col.f32.bf16.bf16.f32 "
        "{%0,%1,%2,%3}, {%4,%5,%6,%7}, {%8,%9}, {%0,%1,%2,%3};"
        : "+f"(c[0]), "+f"(c[1]), "+f"(c[2]), "+f"(c[3])
        : "r"(a[0]), "r"(a[1]), "r"(a[2]), "r"(a[3]), "r"(b[0]), "r"(b[1]));
}
__device__ __forceinline__ void sts32(uint32_t a, uint32_t v) {
    asm volatile("st.shared.b32 [%0], %1;" :: "r"(a), "r"(v) : "memory");
}
__device__ __forceinline__ void sts64(uint32_t a, uint32_t v0, uint32_t v1) {
    asm volatile("st.shared.v2.u32 [%0], {%1, %2};" :: "r"(a), "r"(v0), "r"(v1) : "memory");
}
__device__ __forceinline__ const unsigned char* chunk_src(int g) {
    int l = g & 31;
    return (l < 16) ? (g_Ub + (size_t)l * 32768) : (g_Wb + (size_t)(l - 16) * 32768);
}
__device__ __forceinline__ void issue_chunk(int gc, uint32_t RING, uint32_t BARS) {
    const int l = gc & 31;
    const uint32_t bar = (l < 16) ? (BARS + 8u * (uint32_t)(l & 3))
                                  : (BARS + 32u + 8u * (uint32_t)(l - 16));
    mb_expect(bar, 32768u);
    bulkcp(RING + 32768u * (uint32_t)(l & 3), chunk_src(gc), 32768u, bar);
}

__global__ void prep_uw_kernel(const float* __restrict__ U, const float* __restrict__ W) {
    int idx = blockIdx.x * blockDim.x + threadIdx.x;
    if (idx < 131072) {
        int kc = idx >> 13, rem = idx & 8191, r = rem >> 5, j = rem & 31;
        float2 f = *(const float2*)(U + (size_t)r * DD + kc * 64 + j * 2);
        *(uint32_t*)(g_Ub + kc * 32768 + swz((uint32_t)(r * 128 + j * 4))) = bf2u(__float22bfloat162_rn(f));
    } else {
        int i2 = idx - 131072;
        int t = i2 >> 11, rem = i2 & 2047, dr = rem >> 5, j = rem & 31;
        int nc = t >> 2, kt = t & 3;
        float2 f = *(const float2*)(W + (size_t)(nc * 64 + dr) * RR + kt * 64 + j * 2);
        *(uint32_t*)(g_Wb + t * 8192 + swz((uint32_t)(dr * 128 + j * 4))) = bf2u(__float22bfloat162_rn(f));
    }
}

__global__ __launch_bounds__(NTHR, 1)
void yoshida_mma13_kernel(const float* __restrict__ x, const float* __restrict__ v,
                          const float* __restrict__ force, float* __restrict__ out) {
    extern __shared__ unsigned char dsm[];
    unsigned char* basep = (unsigned char*)(((uintptr_t)dsm + 1023u) & ~(uintptr_t)1023u);
    const uint32_t base = s2u(basep);
    const uint32_t SV   = base;                 // 64KB v bf16: 16 tiles [32 x 64] SW128
    const uint32_t RING = base + 65536u;        // 4 x 32KB unified U/W chunk ring
    const uint32_t H2   = base + 196608u;       // 4 x 4KB h^2 tiles
    const uint32_t BARS = base + 212992u;       // ring mbars[4] @ +0, chunk mbars[16] @ +32

    const int tid = threadIdx.x, wid = tid >> 5, lid = tid & 31;
    const int row0 = blockIdx.x * 32;
    const int q = wid & 7;

    const uint32_t arow0 = (uint32_t)((lid & 15) * 128 + ((lid >> 4) << 4));   // rows 0-15
    const uint32_t arow1 = arow0 + 2048u;                                      // rows 16-31
    const uint32_t brow  = (uint32_t)(((lid & 7) + ((lid >> 4) << 3)) * 128 + (((lid >> 3) & 1) << 4));
    const int hr = lid >> 2, hc2 = (lid & 3) * 2;

    if (tid == 0) {
        #pragma unroll
        for (int i = 0; i < 4; ++i) mb_init(BARS + 8u * i, 1);
        #pragma unroll
        for (int i = 0; i < 16; ++i) mb_init(BARS + 32u + 8u * i, 1);
        fence_async_sh();
        #pragma unroll
        for (int c = 0; c < 4; ++c) issue_chunk(c, RING, BARS);
    }

    for (int i = tid; i < 8192; i += NTHR) {
        int row = i >> 8, rem = i & 255, kc = rem >> 4, jj = rem & 15;
        float4 f = *(const float4*)(v + (size_t)(row0 + row) * DD + kc * 64 + jj * 4);
        sts64(SV + (uint32_t)kc * 4096u + swz((uint32_t)(row * 128 + jj * 8)),
              bf2u(__float22bfloat162_rn(make_float2(f.x, f.y))),
              bf2u(__float22bfloat162_rn(make_float2(f.z, f.w))));
    }
    __syncthreads();

    const float dctab[3] = { (float)K_W1 * K_DT, (float)K_W0 * K_DT, (float)K_W1 * K_DT };

    for (int step = 0; step < 3; ++step) {
        if (wid < 8) {
            // ===== GEMM1 on 8 G warps: 32M x 32N tiles, 8 chunk-pairs =====
            float acc1[8][4];
            #pragma unroll
            for (int t = 0; t < 8; ++t)
                #pragma unroll
                for (int j = 0; j < 4; ++j) acc1[t][j] = 0.f;

            for (int kp = 0; kp < 8; ++kp) {
                if (step > 0 && (kp & 1) == 0)
                    nbar_sync(6 + (kp >> 1), 384);        // owners wrote vn into SV tiles 4r..4r+3
                const int g = step * 32 + kp * 2;
                const int b0 = (kp * 2) & 3;
                const uint32_t ph = (uint32_t)((g >> 2) & 1);
                mb_wait(BARS + 8u * b0, ph);
                mb_wait(BARS + 8u * (b0 + 1), ph);
                #pragma unroll
                for (int cc = 0; cc < 2; ++cc) {
                    const uint32_t Ab = SV + (uint32_t)(kp * 2 + cc) * 4096u;
                    const uint32_t Bb = RING + (uint32_t)(b0 + cc) * 32768u;
                    #pragma unroll
                    for (int ks = 0; ks < 4; ++ks) {
                        uint32_t a0[4], a1[4];
                        ldsm4(a0, Ab + swz(arow0 + ks * 32));
                        ldsm4(a1, Ab + swz(arow1 + ks * 32));
                        #pragma unroll
                        for (int h = 0; h < 2; ++h) {
                            uint32_t bb[4];
                            ldsm4(bb, Bb + swz(brow + (uint32_t)((q * 32 + h * 16) * 128) + ks * 32));
                            mma16816(acc1[h * 2],     a0, bb);
                            mma16816(acc1[h * 2 + 1], a0, bb + 2);
                            mma16816(acc1[4 + h * 2],     a1, bb);
                            mma16816(acc1[4 + h * 2 + 1], a1, bb + 2);
                        }
                    }
                }
                nbar_sync(1, 256);
                if (wid == 0 && lid == 0) {
                    issue_chunk(g + 4, RING, BARS);
                    issue_chunk(g + 5, RING, BARS);
                }
            }

            // ---- h^2 -> H2 bf16 tiles ----
            {
                const uint32_t ht = H2 + (uint32_t)(q >> 1) * 4096u;
                #pragma unroll
                for (int t = 0; t < 8; ++t) {
                    const int mr = t >> 2, h = (t >> 1) & 1, n8 = t & 1;
                    const uint32_t koff = (uint32_t)(((q & 1) * 32 + h * 16 + n8 * 8 + hc2) * 2);
                    float c0 = acc1[t][0], c1 = acc1[t][1], c2 = acc1[t][2], c3 = acc1[t][3];
                    sts32(ht + swz((uint32_t)((mr * 16 + hr) * 128) + koff),
                          bf2u(__float22bfloat162_rn(make_float2(c0 * c0, c1 * c1))));
                    sts32(ht + swz((uint32_t)((mr * 16 + hr + 8) * 128) + koff),
                          bf2u(__float22bfloat162_rn(make_float2(c2 * c2, c3 * c3))));
                }
            }
            nbar_sync(1, 256);                            // H2 visible among G warps
            nbar_arrive(2, 512);                          // release H2 to E warps (non-blocking)
        } else {
            nbar_sync(2, 512);                            // E: acquire H2(step)
        }

        // ===== GEMM2 + reg-direct ew: warp w owns chunk w (one whole 32Mx64N) =====
        {
            const int ci = wid;
            const int gc = step * 32 + 16 + ci;
            mb_wait(BARS + 32u + 8u * (uint32_t)ci, (uint32_t)(step & 1));

            float acc[16][4];
            #pragma unroll
            for (int t = 0; t < 16; ++t)
                #pragma unroll
                for (int j = 0; j < 4; ++j) acc[t][j] = 0.f;

            const uint32_t Bb = RING + (uint32_t)(ci & 3) * 32768u;
            #pragma unroll
            for (int kt = 0; kt < 4; ++kt) {
                const uint32_t At = H2 + (uint32_t)kt * 4096u;
                const uint32_t Bt = Bb + (uint32_t)kt * 8192u;
                #pragma unroll
                for (int ks = 0; ks < 4; ++ks) {
                    uint32_t a0[4], a1[4];
                    ldsm4(a0, At + swz(arow0 + ks * 32));
                    ldsm4(a1, At + swz(arow1 + ks * 32));
                    #pragma unroll
                    for (int nt = 0; nt < 4; ++nt) {
                        uint32_t bb[4];
                        ldsm4(bb, Bt + swz(brow + (uint32_t)((nt * 16) * 128) + ks * 32));
                        mma16816(acc[nt * 2],         a0, bb);
                        mma16816(acc[nt * 2 + 1],     a0, bb + 2);
                        mma16816(acc[8 + nt * 2],     a1, bb);
                        mma16816(acc[8 + nt * 2 + 1], a1, bb + 2);
                    }
                }
            }
            if (lid == 0 && gc + 4 < 96) issue_chunk(gc + 4, RING, BARS);

            // reg-direct elementwise over the owned 32x64 chunk (float2 = full 32B sectors)
            const float dcoef = dctab[step];
            const float* vsrc = (step == 0) ? v : g_vf;
            const uint32_t dst = SV + (uint32_t)ci * 4096u;
            #pragma unroll
            for (int t = 0; t < 16; ++t) {
                const int mr = t >> 3, nt = (t >> 1) & 3, nh = t & 1;
                const int col = nt * 16 + nh * 8 + hc2;
                #pragma unroll
                for (int rh = 0; rh < 2; ++rh) {
                    const int r = mr * 16 + hr + rh * 8;
                    const float g0 = acc[t][rh * 2], g1 = acc[t][rh * 2 + 1];
                    const size_t go = (size_t)(row0 + r) * DD + ci * 64 + col;
                    float2 f2 = *(const float2*)(force + go);
                    float2 v2 = *(const float2*)(vsrc + go);
                    float2 vn;
                    vn.x = v2.x + dcoef * (f2.x - g0);
                    vn.y = v2.y + dcoef * (f2.y - g1);
                    *(float2*)(g_vf + go) = vn;
                    sts32(dst + swz((uint32_t)(r * 128 + col * 2)), bf2u(__float22bfloat162_rn(vn)));
                    float2* ox = (float2*)(out + go);
                    if (step == 0) {
                        float2 tt;
                        tt.x = K_C1f * v2.x + K_C2f * vn.x;
                        tt.y = K_C1f * v2.y + K_C2f * vn.y;
                        *ox = tt;
                    } else if (step == 1) {
                        float2 tt = *ox;
                        tt.x += K_C2f * vn.x; tt.y += K_C2f * vn.y;
                        *ox = tt;
                    } else {
                        float2 tt = *ox;
                        float2 x2 = *(const float2*)(x + go);
                        tt.x = x2.x + K_DT * (tt.x + K_C1f * vn.x);
                        tt.y = x2.y + K_DT * (tt.y + K_C1f * vn.y);
                        *ox = tt;
                        *(float2*)(out + (size_t)BB * DD + go) = vn;
                    }
                }
            }
            if (step < 2) nbar_arrive(6 + (ci >> 2), 384);   // SV tiles 4r..4r+3 hold vn(step)
        }
    }
}

extern "C" void kernel_launch(void* const* d_in, const int* in_sizes, int n_in,
                              void* d_out, int out_size)
{
    const float* x     = (const float*)d_in[0];
    const float* v     = (const float*)d_in[1];
    const float* force = (const float*)d_in[2];
    const float* U     = (const float*)d_in[3];
    const float* W     = (const float*)d_in[4];
    float* out = (float*)d_out;

    const int smem_bytes = 214144;
    cudaFuncSetAttribute(yoshida_mma13_kernel, cudaFuncAttributeMaxDynamicSharedMemorySize, smem_bytes);

    prep_uw_kernel<<<1024, 256>>>(U, W);
    yoshida_mma13_kernel<<<NCTA, NTHR, smem_bytes>>>(x, v, force, out);
}